// round 7
// baseline (speedup 1.0000x reference)
#include <cuda_runtime.h>
#include <math.h>

#define Bn   4096
#define Nn   64
#define Dd   128
#define OCn  64
#define TPB  512
#define LDX  132      // padded row stride for 64x128 node arrays (bank spread)
#define LDA  65       // padded row stride for 64x64 attn

// Transposed GRU weights: [k][g] with g in 0..383 (r | z | n blocks of 128)
__device__ float g_WTih[Dd * 384];
__device__ float g_WThh[Dd * 384];

__global__ void prep_transpose(const float* __restrict__ W_ih,
                               const float* __restrict__ W_hh) {
    int idx = blockIdx.x * blockDim.x + threadIdx.x;   // over 384*128
    int total = 384 * Dd;
    if (idx < total) {
        int g = idx / Dd, k = idx % Dd;
        g_WTih[k * 384 + g] = W_ih[idx];
        g_WThh[k * 384 + g] = W_hh[idx];
    }
}

// ---------- packed f32x2 helpers (sm_103a: 2x FMA throughput vs 3-reg FFMA) ----------
__device__ __forceinline__ unsigned long long bcast2(float x) {
    unsigned long long r;
    asm("mov.b64 %0, {%1, %1};" : "=l"(r) : "f"(x));
    return r;
}
__device__ __forceinline__ void fma2(unsigned long long& d,
                                     unsigned long long a,
                                     unsigned long long b) {
    asm("fma.rn.f32x2 %0, %1, %2, %0;" : "+l"(d) : "l"(a), "l"(b));
}
__device__ __forceinline__ float2 unpack2(unsigned long long v) {
    float2 f;
    asm("mov.b64 {%0, %1}, %2;" : "=f"(f.x), "=f"(f.y) : "l"(v));
    return f;
}
__device__ __forceinline__ float sigmoidf_(float x) {
    return 1.f / (1.f + __expf(-x));
}

// C[4][4] (rows r0..r0+3, cols c0..c0+3) of:
//   oX = shX(64 x 128, stride LDX) @ W1(128 x LDW slice)
//   oS = shS @ W2   (only if DUAL)
// New mapping guarantees: W LDG.128 spans 1 cache line per warp (1 wavefront),
// X LDS.128 has 4 distinct addresses w/ 8-way broadcast.
template<int LDW, bool DUAL>
__device__ __forceinline__ void gemm4x4(const float* __restrict__ shX,
                                        const float* __restrict__ shS,
                                        const float* __restrict__ gW1,
                                        const float* __restrict__ gW2,
                                        int r0, int c0,
                                        float (&oX)[4][4], float (&oS)[4][4]) {
    unsigned long long aX[4][2], aS[4][2];
#pragma unroll
    for (int r = 0; r < 4; r++) {
        aX[r][0] = 0ull; aX[r][1] = 0ull;
        aS[r][0] = 0ull; aS[r][1] = 0ull;
    }
    const char* w1b = reinterpret_cast<const char*>(gW1 + c0);
    const char* w2b = DUAL ? reinterpret_cast<const char*>(gW2 + c0) : nullptr;

#pragma unroll 2
    for (int k0 = 0; k0 < Dd; k0 += 4) {
        float xv[4][4], sv[4][4];
#pragma unroll
        for (int r = 0; r < 4; r++) {
            float4 t = *reinterpret_cast<const float4*>(&shX[(r0 + r) * LDX + k0]);
            xv[r][0] = t.x; xv[r][1] = t.y; xv[r][2] = t.z; xv[r][3] = t.w;
            if constexpr (DUAL) {
                float4 u = *reinterpret_cast<const float4*>(&shS[(r0 + r) * LDX + k0]);
                sv[r][0] = u.x; sv[r][1] = u.y; sv[r][2] = u.z; sv[r][3] = u.w;
            }
        }
#pragma unroll
        for (int kk = 0; kk < 4; kk++) {
            ulonglong2 w1 = *reinterpret_cast<const ulonglong2*>(
                w1b + (size_t)(k0 + kk) * LDW * 4);
            ulonglong2 w2;
            if constexpr (DUAL)
                w2 = *reinterpret_cast<const ulonglong2*>(
                    w2b + (size_t)(k0 + kk) * LDW * 4);
#pragma unroll
            for (int r = 0; r < 4; r++) {
                unsigned long long xb = bcast2(xv[r][kk]);
                fma2(aX[r][0], xb, w1.x);
                fma2(aX[r][1], xb, w1.y);
                if constexpr (DUAL) {
                    unsigned long long sb = bcast2(sv[r][kk]);
                    fma2(aS[r][0], sb, w2.x);
                    fma2(aS[r][1], sb, w2.y);
                }
            }
        }
    }
#pragma unroll
    for (int r = 0; r < 4; r++) {
        float2 p0 = unpack2(aX[r][0]), p1 = unpack2(aX[r][1]);
        oX[r][0] = p0.x; oX[r][1] = p0.y; oX[r][2] = p1.x; oX[r][3] = p1.y;
        if constexpr (DUAL) {
            float2 q0 = unpack2(aS[r][0]), q1 = unpack2(aS[r][1]);
            oS[r][0] = q0.x; oS[r][1] = q0.y; oS[r][2] = q1.x; oS[r][3] = q1.y;
        }
    }
}

__global__ __launch_bounds__(TPB, 1)
void fignn_kernel(const float* __restrict__ h_g,
                  const float* __restrict__ a_src,
                  const float* __restrict__ a_dst,
                  const float* __restrict__ w_g,
                  const float* __restrict__ bias_g,
                  const float* __restrict__ b_ih,
                  const float* __restrict__ b_hh,
                  const float* __restrict__ mlp1_w,
                  const float* __restrict__ mlp1_b,
                  const float* __restrict__ mlp2_w,
                  const float* __restrict__ mlp2_b,
                  const int* __restrict__ steps_p,
                  float* __restrict__ out) {
    extern __shared__ float sm[];
    float* sh_h    = sm;                        // 64*LDX
    float* sh_s    = sh_h  + Nn * LDX;
    float* sh_t1   = sh_s  + Nn * LDX;          // s@w + misc scratch
    float* sh_t2   = sh_t1 + Nn * LDX;          // A = attn@(s@w)+bias
    float* sh_attn = sh_t2 + Nn * LDX;          // 64*LDA

    const int b    = blockIdx.x;
    const int tid  = threadIdx.x;
    const int lane = tid & 31;
    const int wid  = tid >> 5;
    // warp tile: 16 rows x 32 cols; lane = rg*8 + cg
    const int rb = wid >> 2, cb = wid & 3;
    const int rg = lane >> 3, cg = lane & 7;
    const int r0 = rb * 16 + rg * 4;            // rows 0..63
    const int c0 = cb * 32 + cg * 4;            // cols 0..127

    const float* hb = h_g + (size_t)b * Nn * Dd;

    // load h -> shared (padded rows); s = h
    for (int i = tid; i < Nn * Dd / 4; i += TPB) {
        int row = i >> 5;                        // i/(128/4)
        int col4 = i & 31;
        float4 v = reinterpret_cast<const float4*>(hb)[i];
        *reinterpret_cast<float4*>(&sh_h[row * LDX + col4 * 4]) = v;
        *reinterpret_cast<float4*>(&sh_s[row * LDX + col4 * 4]) = v;
    }
    __syncthreads();

    // attn_src / attn_dst (stored in t1[0..63] / t1[64..127])
    if (tid < 128) {
        int i = tid & 63;
        const float* vec = (tid < 64) ? a_src : a_dst;
        float acc = 0.f;
#pragma unroll 8
        for (int k = 0; k < Dd; k++) acc += sh_h[i * LDX + k] * vec[k];
        sh_t1[(tid < 64 ? 0 : 64) + i] = acc;
    }
    __syncthreads();

    // attn rows: leaky_relu, zero diagonal (mask-multiply), softmax
    for (int row = wid; row < Nn; row += 16) {
        float srci = sh_t1[row];
        int j0 = lane, j1 = lane + 32;
        float v0 = srci + sh_t1[64 + j0];
        float v1 = srci + sh_t1[64 + j1];
        v0 = v0 > 0.f ? v0 : 0.2f * v0;
        v1 = v1 > 0.f ? v1 : 0.2f * v1;
        if (j0 == row) v0 = 0.f;
        if (j1 == row) v1 = 0.f;
        float m = fmaxf(v0, v1);
#pragma unroll
        for (int o = 16; o > 0; o >>= 1) m = fmaxf(m, __shfl_xor_sync(0xffffffffu, m, o));
        float e0 = __expf(v0 - m), e1 = __expf(v1 - m);
        float sum2 = e0 + e1;
#pragma unroll
        for (int o = 16; o > 0; o >>= 1) sum2 += __shfl_xor_sync(0xffffffffu, sum2, o);
        float inv = 1.f / sum2;
        sh_attn[row * LDA + j0] = e0 * inv;
        sh_attn[row * LDA + j1] = e1 * inv;
    }
    __syncthreads();

    int steps = steps_p ? *steps_p : 3;
    float dummy[4][4];

    for (int it = 0; it < steps; it++) {
        // ---- 1) t1 = s @ w ----
        float accw[4][4];
        gemm4x4<Dd, false>(sh_s, nullptr, w_g, nullptr, r0, c0, accw, dummy);
#pragma unroll
        for (int r = 0; r < 4; r++)
            *reinterpret_cast<float4*>(&sh_t1[(r0 + r) * LDX + c0]) =
                make_float4(accw[r][0], accw[r][1], accw[r][2], accw[r][3]);
        __syncthreads();

        // ---- 2) t2 = attn @ t1 + bias ----
        float acca[4][4] = {};
#pragma unroll 4
        for (int j = 0; j < Nn; j++) {
            float4 tv = *reinterpret_cast<const float4*>(&sh_t1[j * LDX + c0]);
#pragma unroll
            for (int r = 0; r < 4; r++) {
                float av = sh_attn[(r0 + r) * LDA + j];
                acca[r][0] += av * tv.x; acca[r][1] += av * tv.y;
                acca[r][2] += av * tv.z; acca[r][3] += av * tv.w;
            }
        }
        float4 bz = *reinterpret_cast<const float4*>(&bias_g[c0]);
#pragma unroll
        for (int r = 0; r < 4; r++)
            *reinterpret_cast<float4*>(&sh_t2[(r0 + r) * LDX + c0]) =
                make_float4(acca[r][0] + bz.x, acca[r][1] + bz.y,
                            acca[r][2] + bz.z, acca[r][3] + bz.w);
        __syncthreads();

        // ---- 3) GRU gates (R/Z/N kept in registers; thread owns same cells) ----
        float gi[4][4], gh[4][4], Rr[4][4], Zz[4][4], Nv[4][4];

        // R gate: cols 0..127 of 384
        gemm4x4<384, true>(sh_t2, sh_s, g_WTih, g_WThh, r0, c0, gi, gh);
        {
            float4 bi = *reinterpret_cast<const float4*>(&b_ih[c0]);
            float4 bh = *reinterpret_cast<const float4*>(&b_hh[c0]);
            float bif[4] = {bi.x, bi.y, bi.z, bi.w};
            float bhf[4] = {bh.x, bh.y, bh.z, bh.w};
#pragma unroll
            for (int r = 0; r < 4; r++)
#pragma unroll
                for (int c = 0; c < 4; c++)
                    Rr[r][c] = sigmoidf_(gi[r][c] + bif[c] + gh[r][c] + bhf[c]);
        }
        // Z gate: cols 128..255
        gemm4x4<384, true>(sh_t2, sh_s, g_WTih + 128, g_WThh + 128, r0, c0, gi, gh);
        {
            float4 bi = *reinterpret_cast<const float4*>(&b_ih[128 + c0]);
            float4 bh = *reinterpret_cast<const float4*>(&b_hh[128 + c0]);
            float bif[4] = {bi.x, bi.y, bi.z, bi.w};
            float bhf[4] = {bh.x, bh.y, bh.z, bh.w};
#pragma unroll
            for (int r = 0; r < 4; r++)
#pragma unroll
                for (int c = 0; c < 4; c++)
                    Zz[r][c] = sigmoidf_(gi[r][c] + bif[c] + gh[r][c] + bhf[c]);
        }
        // N gate: cols 256..383 ; n = tanh(i_n + r * h_n)
        gemm4x4<384, true>(sh_t2, sh_s, g_WTih + 256, g_WThh + 256, r0, c0, gi, gh);
        {
            float4 bi = *reinterpret_cast<const float4*>(&b_ih[256 + c0]);
            float4 bh = *reinterpret_cast<const float4*>(&b_hh[256 + c0]);
            float bif[4] = {bi.x, bi.y, bi.z, bi.w};
            float bhf[4] = {bh.x, bh.y, bh.z, bh.w};
#pragma unroll
            for (int r = 0; r < 4; r++)
#pragma unroll
                for (int c = 0; c < 4; c++)
                    Nv[r][c] = tanhf(gi[r][c] + bif[c] +
                                     Rr[r][c] * (gh[r][c] + bhf[c]));
        }

        // ---- 4) s = (1-z)*n + z*s + h ----
        float sold[4][4], hold[4][4];
#pragma unroll
        for (int r = 0; r < 4; r++) {
            float4 so = *reinterpret_cast<const float4*>(&sh_s[(r0 + r) * LDX + c0]);
            float4 ho = *reinterpret_cast<const float4*>(&sh_h[(r0 + r) * LDX + c0]);
            sold[r][0] = so.x; sold[r][1] = so.y; sold[r][2] = so.z; sold[r][3] = so.w;
            hold[r][0] = ho.x; hold[r][1] = ho.y; hold[r][2] = ho.z; hold[r][3] = ho.w;
        }
        __syncthreads();
#pragma unroll
        for (int r = 0; r < 4; r++) {
            float v[4];
#pragma unroll
            for (int c = 0; c < 4; c++)
                v[c] = (1.f - Zz[r][c]) * Nv[r][c] + Zz[r][c] * sold[r][c] + hold[r][c];
            *reinterpret_cast<float4*>(&sh_s[(r0 + r) * LDX + c0]) =
                make_float4(v[0], v[1], v[2], v[3]);
        }
        __syncthreads();
    }

    // ---- readout ----
    if (tid < Nn) {
        float acc = 0.f;
#pragma unroll 8
        for (int k = 0; k < Dd; k++) acc += sh_s[tid * LDX + k] * mlp2_w[k];
        sh_t1[tid] = acc + mlp2_b[0];
    }
    __syncthreads();
    if (tid < Dd) {
        float acc = 0.f;
#pragma unroll
        for (int n = 0; n < Nn; n++) acc += sh_t1[n] * sh_s[n * LDX + tid];
        sh_t1[128 + tid] = acc;
    }
    __syncthreads();
    if (tid < OCn) {
        float acc = 0.f;
#pragma unroll 4
        for (int k = 0; k < Dd; k++) acc += sh_t1[128 + k] * mlp1_w[k * OCn + tid];
        float wsum = 0.f;
#pragma unroll
        for (int n = 0; n < Nn; n++) wsum += sh_t1[n];
        out[(size_t)b * OCn + tid] = acc + wsum * mlp1_b[tid];
    }
}

extern "C" void kernel_launch(void* const* d_in, const int* in_sizes, int n_in,
                              void* d_out, int out_size) {
    const float* h      = (const float*)d_in[0];
    // d_in[1] = adj : unused by the reference math (only its shape is used)
    const float* a_src  = (const float*)d_in[2];
    const float* a_dst  = (const float*)d_in[3];
    const float* w      = (const float*)d_in[4];
    const float* bias   = (const float*)d_in[5];
    const float* W_ih   = (const float*)d_in[6];
    const float* W_hh   = (const float*)d_in[7];
    const float* b_ih   = (const float*)d_in[8];
    const float* b_hh   = (const float*)d_in[9];
    const float* mlp1_w = (const float*)d_in[10];
    const float* mlp1_b = (const float*)d_in[11];
    const float* mlp2_w = (const float*)d_in[12];
    const float* mlp2_b = (const float*)d_in[13];
    const int*   steps  = (n_in > 14) ? (const int*)d_in[14] : nullptr;

    int batches = in_sizes[0] / (Nn * Dd);

    // smem: 4 node arrays (64*132) + attn (64*65), floats
    int smem_bytes = (4 * Nn * LDX + Nn * LDA) * 4;

    cudaFuncSetAttribute(fignn_kernel,
                         cudaFuncAttributeMaxDynamicSharedMemorySize, smem_bytes);

    prep_transpose<<<(384 * Dd + 255) / 256, 256>>>(W_ih, W_hh);
    fignn_kernel<<<batches, TPB, smem_bytes>>>(h, a_src, a_dst, w, bias,
                                               b_ih, b_hh, mlp1_w, mlp1_b,
                                               mlp2_w, mlp2_b, steps,
                                               (float*)d_out);
}

// round 9
// speedup vs baseline: 2.2448x; 2.2448x over previous
#include <cuda_runtime.h>
#include <cuda_bf16.h>
#include <math.h>
#include <stdint.h>

#define THR 256

// ---- smem byte offsets (all 16B aligned where ldmatrix touches them) ----
#define OFF_SCR   0        // 256 floats scratch
#define OFF_BR    1024     // 128 f32
#define OFF_BZ    1536
#define OFF_BIN   2048
#define OFF_BHN   2560
#define OFF_MSGB  3072     // 128 f32
#define OFF_ATT   3584     // attn: 64 x 72 bf16 hi (9216B), lo at +9216
#define OFF_SWT   22016    // SW^T: 128 x 72 bf16 hi (18432B), lo at +18432
#define OFF_S     58880    // S:    64 x 136 bf16 hi (17408B), lo at +17408
#define OFF_AM    93696    // Amsg: 64 x 136 bf16 hi, lo at +17408
#define OFF_H     128512   // h residual fp32 64x128 (32768B)
#define SMEM_TOTAL 161280

#define STB_X  272     // byte stride for 128-col arrays (136 bf16)
#define STB_W  144     // byte stride for 64-col arrays  (72 bf16)
#define HL_X   17408   // hi->lo offset for S/AM
#define HL_ATT 9216
#define HL_SWT 18432

// weights in A-fragment-native layout: index ((tile*64 + mt*8 + kt)*32 + lane)
// tile: 0 = w^T, 1..3 = W_ih r/z/n, 4..6 = W_hh r/z/n
__device__ __align__(16) uint4 g_wf_hi[7 * 64 * 32];
__device__ __align__(16) uint4 g_wf_lo[7 * 64 * 32];

__device__ __forceinline__ float wfetch(int tile, int g, int k,
                                        const float* w, const float* W_ih,
                                        const float* W_hh) {
    if (tile == 0) return w[k * 128 + g];                    // w^T[d][k]
    if (tile <= 3) return W_ih[((tile - 1) * 128 + g) * 128 + k];
    return W_hh[((tile - 4) * 128 + g) * 128 + k];
}

__global__ void prep_weights(const float* __restrict__ w,
                             const float* __restrict__ W_ih,
                             const float* __restrict__ W_hh) {
    int idx = blockIdx.x * blockDim.x + threadIdx.x;
    if (idx >= 7 * 64 * 32) return;
    int lane = idx & 31, kt = (idx >> 5) & 7, mt = (idx >> 8) & 7, tile = idx >> 11;
    int g = mt * 16 + (lane >> 2), k = kt * 16 + (lane & 3) * 2;
    const int dr[4] = {0, 8, 0, 8};   // a0,a1,a2,a3 row offsets
    const int dc[4] = {0, 0, 8, 8};   // col offsets
    uint32_t hi[4], lo[4];
#pragma unroll
    for (int a = 0; a < 4; a++) {
        float v0 = wfetch(tile, g + dr[a], k + dc[a], w, W_ih, W_hh);
        float v1 = wfetch(tile, g + dr[a], k + dc[a] + 1, w, W_ih, W_hh);
        __nv_bfloat16 h0 = __float2bfloat16(v0);
        __nv_bfloat16 l0 = __float2bfloat16(v0 - __bfloat162float(h0));
        __nv_bfloat16 h1 = __float2bfloat16(v1);
        __nv_bfloat16 l1 = __float2bfloat16(v1 - __bfloat162float(h1));
        __nv_bfloat162 ph(h0, h1), pl(l0, l1);
        hi[a] = *reinterpret_cast<uint32_t*>(&ph);
        lo[a] = *reinterpret_cast<uint32_t*>(&pl);
    }
    g_wf_hi[idx] = make_uint4(hi[0], hi[1], hi[2], hi[3]);
    g_wf_lo[idx] = make_uint4(lo[0], lo[1], lo[2], lo[3]);
}

// ---- device helpers ----
__device__ __forceinline__ uint32_t smem_u32(const void* p) {
    uint32_t a;
    asm("{ .reg .u64 t; cvta.to.shared.u64 t, %1; cvt.u32.u64 %0, t; }" : "=r"(a) : "l"(p));
    return a;
}
__device__ __forceinline__ void ldsm4(uint32_t* r, uint32_t a) {
    asm volatile("ldmatrix.sync.aligned.m8n8.x4.shared.b16 {%0,%1,%2,%3}, [%4];"
                 : "=r"(r[0]), "=r"(r[1]), "=r"(r[2]), "=r"(r[3]) : "r"(a));
}
__device__ __forceinline__ void mma_bf16(float* c, const uint32_t* a,
                                         uint32_t b0, uint32_t b1) {
    asm volatile("mma.sync.aligned.m16n8k16.row.col.f32.bf16.bf16.f32 "
                 "{%0,%1,%2,%3}, {%4,%5,%6,%7}, {%8,%9}, {%0,%1,%2,%3};"
                 : "+f"(c[0]), "+f"(c[1]), "+f"(c[2]), "+f"(c[3])
                 : "r"(a[0]), "r"(a[1]), "r"(a[2]), "r"(a[3]), "r"(b0), "r"(b1));
}
__device__ __forceinline__ float rbf(const char* p) {
    return __bfloat162float(*reinterpret_cast<const __nv_bfloat16*>(p));
}
__device__ __forceinline__ void st_split_pair(char* hi, char* lo, float v0, float v1) {
    __nv_bfloat16 h0 = __float2bfloat16(v0);
    __nv_bfloat16 l0 = __float2bfloat16(v0 - __bfloat162float(h0));
    __nv_bfloat16 h1 = __float2bfloat16(v1);
    __nv_bfloat16 l1 = __float2bfloat16(v1 - __bfloat162float(h1));
    __nv_bfloat162 ph(h0, h1), pl(l0, l1);
    *reinterpret_cast<uint32_t*>(hi) = *reinterpret_cast<uint32_t*>(&ph);
    *reinterpret_cast<uint32_t*>(lo) = *reinterpret_cast<uint32_t*>(&pl);
}
__device__ __forceinline__ float sigmoidf_(float x) { return 1.f / (1.f + __expf(-x)); }

__global__ __launch_bounds__(THR, 1)
void fignn_mma(const float* __restrict__ h_g,
               const float* __restrict__ a_src, const float* __restrict__ a_dst,
               const float* __restrict__ bias_g,
               const float* __restrict__ b_ih, const float* __restrict__ b_hh,
               const float* __restrict__ mlp1_w, const float* __restrict__ mlp1_b,
               const float* __restrict__ mlp2_w, const float* __restrict__ mlp2_b,
               const int* __restrict__ steps_p, float* __restrict__ out) {
    extern __shared__ char smem[];
    const uint32_t sb = smem_u32(smem);
    const int tid = threadIdx.x, lane = tid & 31, wid = tid >> 5;
    const int b = blockIdx.x;
    const float* hb = h_g + (size_t)b * 64 * 128;

    float* scr  = reinterpret_cast<float*>(smem + OFF_SCR);
    float* vbr  = reinterpret_cast<float*>(smem + OFF_BR);
    float* vbz  = reinterpret_cast<float*>(smem + OFF_BZ);
    float* vbin = reinterpret_cast<float*>(smem + OFF_BIN);
    float* vbhn = reinterpret_cast<float*>(smem + OFF_BHN);
    float* msgb = reinterpret_cast<float*>(smem + OFF_MSGB);

    // ---- init: h -> H fp32 + S bf16 split ----
    for (int t = tid; t < 2048; t += THR) {
        float4 v = reinterpret_cast<const float4*>(hb)[t];
        int i = t >> 5, k0 = (t & 31) * 4;
        *reinterpret_cast<float4*>(smem + OFF_H + (i * 128 + k0) * 4) = v;
        char* p = smem + OFF_S + i * STB_X + k0 * 2;
        st_split_pair(p, p + HL_X, v.x, v.y);
        st_split_pair(p + 4, p + 4 + HL_X, v.z, v.w);
    }
    if (tid < 128) {
        vbr[tid]  = b_ih[tid] + b_hh[tid];
        vbz[tid]  = b_ih[128 + tid] + b_hh[128 + tid];
        vbin[tid] = b_ih[256 + tid];
        vbhn[tid] = b_hh[256 + tid];
        msgb[tid] = bias_g[tid];
    }
    // attention dots
    for (int idx = wid; idx < 128; idx += 8) {
        int i = idx & 63;
        const float* vec = (idx < 64) ? a_src : a_dst;
        float acc = 0.f;
#pragma unroll
        for (int m = 0; m < 4; m++)
            acc += hb[i * 128 + lane + m * 32] * vec[lane + m * 32];
#pragma unroll
        for (int o = 16; o > 0; o >>= 1) acc += __shfl_xor_sync(0xffffffffu, acc, o);
        if (lane == 0) scr[idx] = acc;
    }
    __syncthreads();
    // softmax rows -> ATT bf16 split
    for (int row = wid; row < 64; row += 8) {
        float srci = scr[row];
        int j0 = lane, j1 = lane + 32;
        float v0 = srci + scr[64 + j0], v1 = srci + scr[64 + j1];
        v0 = v0 > 0.f ? v0 : 0.2f * v0;
        v1 = v1 > 0.f ? v1 : 0.2f * v1;
        if (j0 == row) v0 = 0.f;
        if (j1 == row) v1 = 0.f;
        float m = fmaxf(v0, v1);
#pragma unroll
        for (int o = 16; o > 0; o >>= 1) m = fmaxf(m, __shfl_xor_sync(0xffffffffu, m, o));
        float e0 = __expf(v0 - m), e1 = __expf(v1 - m);
        float s2 = e0 + e1;
#pragma unroll
        for (int o = 16; o > 0; o >>= 1) s2 += __shfl_xor_sync(0xffffffffu, s2, o);
        float inv = 1.f / s2;
        char* p0 = smem + OFF_ATT + row * STB_W + j0 * 2;
        char* p1 = smem + OFF_ATT + row * STB_W + j1 * 2;
        float a0 = e0 * inv, a1 = e1 * inv;
        __nv_bfloat16 hh = __float2bfloat16(a0);
        *reinterpret_cast<__nv_bfloat16*>(p0) = hh;
        *reinterpret_cast<__nv_bfloat16*>(p0 + HL_ATT) =
            __float2bfloat16(a0 - __bfloat162float(hh));
        hh = __float2bfloat16(a1);
        *reinterpret_cast<__nv_bfloat16*>(p1) = hh;
        *reinterpret_cast<__nv_bfloat16*>(p1 + HL_ATT) =
            __float2bfloat16(a1 - __bfloat162float(hh));
    }
    __syncthreads();

    // per-lane fragment offsets
    const int rB = (lane & 7) + ((lane >> 4) << 3);
    const int cB = ((lane >> 3) & 1) * 8;
    const int rA = (lane & 7) + ((lane >> 3) & 1) * 8;
    const int cA = ((lane >> 4) & 1) * 8;
    const uint32_t bOffX = rB * STB_X + cB * 2;
    const uint32_t bOffW = rB * STB_W + cB * 2;
    const uint32_t aOffW = rA * STB_W + cA * 2;
    const int r_ = lane >> 2, c2 = (lane & 3) * 2;

    const int steps = steps_p ? steps_p[0] : 3;

    for (int it = 0; it < steps; it++) {
        // ===== G1: SWT[d][j] = sum_k wT[d][k] * S[j][k]  (M=128,N=64,K=128) =====
        {
            float acc[8][4];
#pragma unroll
            for (int a = 0; a < 8; a++)
#pragma unroll
                for (int e = 0; e < 4; e++) acc[a][e] = 0.f;
            for (int t3 = 0; t3 < 3; t3++) {
                const uint4* wb = (t3 == 2) ? g_wf_lo : g_wf_hi;
                uint32_t Bb = sb + OFF_S + ((t3 == 1) ? HL_X : 0) + bOffX;
#pragma unroll
                for (int kt = 0; kt < 8; kt++) {
                    uint4 af = wb[((wid * 8 + kt) << 5) + lane];
#pragma unroll
                    for (int n2 = 0; n2 < 4; n2++) {
                        uint32_t bf[4];
                        ldsm4(bf, Bb + n2 * 16 * STB_X + kt * 32);
                        mma_bf16(acc[n2 * 2], reinterpret_cast<uint32_t*>(&af), bf[0], bf[1]);
                        mma_bf16(acc[n2 * 2 + 1], reinterpret_cast<uint32_t*>(&af), bf[2], bf[3]);
                    }
                }
            }
#pragma unroll
            for (int nt = 0; nt < 8; nt++) {
                int d0 = wid * 16 + r_, j = nt * 8 + c2;
                char* p = smem + OFF_SWT + d0 * STB_W + j * 2;
                st_split_pair(p, p + HL_SWT, acc[nt][0], acc[nt][1]);
                p += 8 * STB_W;
                st_split_pair(p, p + HL_SWT, acc[nt][2], acc[nt][3]);
            }
        }
        __syncthreads();
        // ===== G2: AM[i][d] = sum_j attn[i][j] * SWT[d][j] + msgb  (M=64,N=128,K=64) =====
        {
            float acc[8][4];
#pragma unroll
            for (int a = 0; a < 8; a++)
#pragma unroll
                for (int e = 0; e < 4; e++) acc[a][e] = 0.f;
            int i0 = (wid & 3) * 16, dbase = (wid >> 2) * 64;
            for (int t3 = 0; t3 < 3; t3++) {
                uint32_t Ab = sb + OFF_ATT + ((t3 == 2) ? HL_ATT : 0) + aOffW + i0 * STB_W;
                uint32_t Bb = sb + OFF_SWT + ((t3 == 1) ? HL_SWT : 0) + bOffW + dbase * STB_W;
#pragma unroll
                for (int kt = 0; kt < 4; kt++) {
                    uint32_t af[4];
                    ldsm4(af, Ab + kt * 32);
#pragma unroll
                    for (int n2 = 0; n2 < 4; n2++) {
                        uint32_t bf[4];
                        ldsm4(bf, Bb + n2 * 16 * STB_W + kt * 32);
                        mma_bf16(acc[n2 * 2], af, bf[0], bf[1]);
                        mma_bf16(acc[n2 * 2 + 1], af, bf[2], bf[3]);
                    }
                }
            }
#pragma unroll
            for (int nt = 0; nt < 8; nt++) {
                int d = dbase + nt * 8 + c2;
                float m0 = msgb[d], m1 = msgb[d + 1];
                int itop = i0 + r_;
                char* p = smem + OFF_AM + itop * STB_X + d * 2;
                st_split_pair(p, p + HL_X, acc[nt][0] + m0, acc[nt][1] + m1);
                p += 8 * STB_X;
                st_split_pair(p, p + HL_X, acc[nt][2] + m0, acc[nt][3] + m1);
            }
        }
        __syncthreads();
        // ===== gates: two passes over node halves; D[g][i], warp owns g-tile =====
        for (int p = 0; p < 2; p++) {
            float acc[4][4][4];   // set(r,z,in,hn) x nt x elem
#pragma unroll
            for (int s = 0; s < 4; s++)
#pragma unroll
                for (int a = 0; a < 4; a++)
#pragma unroll
                    for (int e = 0; e < 4; e++) acc[s][a][e] = 0.f;
#pragma unroll
            for (int gate = 0; gate < 3; gate++) {
#pragma unroll
                for (int src = 0; src < 2; src++) {
                    const int set = (gate < 2) ? gate : (2 + src);
                    const int tile = 1 + gate + 3 * src;
                    const uint32_t BbaseOff = (src == 0) ? OFF_AM : OFF_S;
                    for (int t3 = 0; t3 < 3; t3++) {
                        const uint4* wb = (t3 == 2) ? g_wf_lo : g_wf_hi;
                        uint32_t Bb = sb + BbaseOff + ((t3 == 1) ? HL_X : 0) + bOffX +
                                      p * 32 * STB_X;
#pragma unroll
                        for (int kt = 0; kt < 8; kt++) {
                            uint4 af = wb[((tile * 64 + wid * 8 + kt) << 5) + lane];
#pragma unroll
                            for (int n2 = 0; n2 < 2; n2++) {
                                uint32_t bf[4];
                                ldsm4(bf, Bb + n2 * 16 * STB_X + kt * 32);
                                mma_bf16(acc[set][n2 * 2], reinterpret_cast<uint32_t*>(&af),
                                         bf[0], bf[1]);
                                mma_bf16(acc[set][n2 * 2 + 1], reinterpret_cast<uint32_t*>(&af),
                                         bf[2], bf[3]);
                            }
                        }
                    }
                }
            }
            __syncthreads();   // all warps done reading S/AM rows for this pass
            // GRU update for i in [32p, 32p+32)
#pragma unroll
            for (int nt = 0; nt < 4; nt++) {
#pragma unroll
                for (int q = 0; q < 2; q++) {
                    int g = wid * 16 + r_ + q * 8;
                    float bR = vbr[g], bZ = vbz[g], bI = vbin[g], bH = vbhn[g];
#pragma unroll
                    for (int e = 0; e < 2; e++) {
                        int i = 32 * p + nt * 8 + c2 + e;
                        int ci = q * 2 + e;
                        float R  = sigmoidf_(acc[0][nt][ci] + bR);
                        float Z  = sigmoidf_(acc[1][nt][ci] + bZ);
                        float Nv = tanhf(acc[2][nt][ci] + bI + R * (acc[3][nt][ci] + bH));
                        char* sp = smem + OFF_S + i * STB_X + g * 2;
                        float sold = rbf(sp) + rbf(sp + HL_X);
                        float hres = *reinterpret_cast<float*>(smem + OFF_H + (i * 128 + g) * 4);
                        float sv = (1.f - Z) * Nv + Z * sold + hres;
                        __nv_bfloat16 hh = __float2bfloat16(sv);
                        *reinterpret_cast<__nv_bfloat16*>(sp) = hh;
                        *reinterpret_cast<__nv_bfloat16*>(sp + HL_X) =
                            __float2bfloat16(sv - __bfloat162float(hh));
                    }
                }
            }
        }
        __syncthreads();
    }

    // ===== readout =====
    if (tid < 64) {
        float acc = 0.f;
#pragma unroll 8
        for (int k = 0; k < 128; k++) {
            char* sp = smem + OFF_S + tid * STB_X + k * 2;
            acc += (rbf(sp) + rbf(sp + HL_X)) * mlp2_w[k];
        }
        scr[tid] = acc + mlp2_b[0];
    }
    __syncthreads();
    if (tid < 128) {
        float acc = 0.f;
#pragma unroll 4
        for (int n = 0; n < 64; n++) {
            char* sp = smem + OFF_S + n * STB_X + tid * 2;
            acc += scr[n] * (rbf(sp) + rbf(sp + HL_X));
        }
        scr[64 + tid] = acc;
    }
    __syncthreads();
    if (tid < 64) {
        float acc = 0.f;
#pragma unroll 4
        for (int d = 0; d < 128; d++) acc += scr[64 + d] * mlp1_w[d * 64 + tid];
        float ws = 0.f;
#pragma unroll
        for (int n = 0; n < 64; n++) ws += scr[n];
        out[(size_t)b * 64 + tid] = acc + ws * mlp1_b[tid];
    }
}

extern "C" void kernel_launch(void* const* d_in, const int* in_sizes, int n_in,
                              void* d_out, int out_size) {
    const float* h      = (const float*)d_in[0];
    // d_in[1] = adj: unused by the math (shape only)
    const float* a_src  = (const float*)d_in[2];
    const float* a_dst  = (const float*)d_in[3];
    const float* w      = (const float*)d_in[4];
    const float* bias   = (const float*)d_in[5];
    const float* W_ih   = (const float*)d_in[6];
    const float* W_hh   = (const float*)d_in[7];
    const float* b_ih   = (const float*)d_in[8];
    const float* b_hh   = (const float*)d_in[9];
    const float* mlp1_w = (const float*)d_in[10];
    const float* mlp1_b = (const float*)d_in[11];
    const float* mlp2_w = (const float*)d_in[12];
    const float* mlp2_b = (const float*)d_in[13];
    const int*   steps  = (n_in > 14) ? (const int*)d_in[14] : nullptr;

    int batches = in_sizes[0] / (64 * 128);

    cudaFuncSetAttribute(fignn_mma, cudaFuncAttributeMaxDynamicSharedMemorySize,
                         SMEM_TOTAL);
    prep_weights<<<(7 * 64 * 32 + 255) / 256, 256>>>(w, W_ih, W_hh);
    fignn_mma<<<batches, THR, SMEM_TOTAL>>>(h, a_src, a_dst, bias, b_ih, b_hh,
                                            mlp1_w, mlp1_b, mlp2_w, mlp2_b,
                                            steps, (float*)d_out);
}